// round 3
// baseline (speedup 1.0000x reference)
#include <cuda_runtime.h>

// Problem constants (fixed by setup_inputs): B=96, N_NODE=512, D=128, n_steps=5
#define NB 96
#define NN 512
#define ND 128
#define NROWS (NB * NN)            // 49152
#define NSTEPS 5

// Scratch (allocation-free rule: __device__ globals)
__device__ float g_hp[NROWS * ND];      // h @ Wp^T
__device__ float g_neigh[NROWS * ND];   // mask @ hp + n*bp
__device__ float g_Wt[7 * ND * ND];     // transposed weights: [k][j] = W[j][k]
// order: 0=Wz 1=Uz 2=Wr 3=Ur 4=Wh 5=Uh 6=Wp

typedef unsigned long long ull;

__device__ __forceinline__ ull pack2(float lo, float hi) {
    ull r; asm("mov.b64 %0, {%1,%2};" : "=l"(r) : "f"(lo), "f"(hi)); return r;
}
__device__ __forceinline__ void fma2(ull& d, ull a, ull b) {
    asm("fma.rn.f32x2 %0, %1, %2, %0;" : "+l"(d) : "l"(a), "l"(b));
}
__device__ __forceinline__ void unpack2(ull v, float& lo, float& hi) {
    asm("mov.b64 {%0,%1}, %2;" : "=f"(lo), "=f"(hi) : "l"(v));
}
__device__ __forceinline__ float sigmoidf_(float x) { return 1.0f / (1.0f + __expf(-x)); }

// ---------------------------------------------------------------------------
// Core micro-kernel: 64-row x 128-col block tile, 256 threads (16x16),
// per-thread 4 rows x 8 cols (cols c0..c0+3 and c0+64..c0+67, c0 = 4*tx).
// sX: [rows][LDX] row-major (k contiguous). sW: [K][132] k-major (j contiguous).
// acc[i][p] holds a packed f32x2 pair. Conflict-free: w loads are float4 at
// 16B lane stride; a loads broadcast within half-warp.
// ---------------------------------------------------------------------------
template <int LDX>
__device__ __forceinline__ void mma_block(const float* __restrict__ sX,
                                          const float* __restrict__ sW,
                                          int K, int r0, int c0, ull acc[4][4]) {
#pragma unroll 2
    for (int k = 0; k < K; k += 4) {
        float4 a0 = *(const float4*)(sX + (r0 + 0) * LDX + k);
        float4 a1 = *(const float4*)(sX + (r0 + 1) * LDX + k);
        float4 a2 = *(const float4*)(sX + (r0 + 2) * LDX + k);
        float4 a3 = *(const float4*)(sX + (r0 + 3) * LDX + k);
#pragma unroll
        for (int kk = 0; kk < 4; kk++) {
            const float* wr = sW + (k + kk) * 132;
            float4 w0 = *(const float4*)(wr + c0);
            float4 w1 = *(const float4*)(wr + c0 + 64);
            ull wp0 = pack2(w0.x, w0.y), wp1 = pack2(w0.z, w0.w);
            ull wp2 = pack2(w1.x, w1.y), wp3 = pack2(w1.z, w1.w);
            float e0 = (kk == 0) ? a0.x : (kk == 1) ? a0.y : (kk == 2) ? a0.z : a0.w;
            float e1 = (kk == 0) ? a1.x : (kk == 1) ? a1.y : (kk == 2) ? a1.z : a1.w;
            float e2 = (kk == 0) ? a2.x : (kk == 1) ? a2.y : (kk == 2) ? a2.z : a2.w;
            float e3 = (kk == 0) ? a3.x : (kk == 1) ? a3.y : (kk == 2) ? a3.z : a3.w;
            ull ap0 = pack2(e0, e0), ap1 = pack2(e1, e1);
            ull ap2 = pack2(e2, e2), ap3 = pack2(e3, e3);
            fma2(acc[0][0], ap0, wp0); fma2(acc[0][1], ap0, wp1);
            fma2(acc[0][2], ap0, wp2); fma2(acc[0][3], ap0, wp3);
            fma2(acc[1][0], ap1, wp0); fma2(acc[1][1], ap1, wp1);
            fma2(acc[1][2], ap1, wp2); fma2(acc[1][3], ap1, wp3);
            fma2(acc[2][0], ap2, wp0); fma2(acc[2][1], ap2, wp1);
            fma2(acc[2][2], ap2, wp2); fma2(acc[2][3], ap2, wp3);
            fma2(acc[3][0], ap3, wp0); fma2(acc[3][1], ap3, wp1);
            fma2(acc[3][2], ap3, wp2); fma2(acc[3][3], ap3, wp3);
        }
    }
}

__device__ __forceinline__ void zero_acc(ull acc[4][4]) {
#pragma unroll
    for (int i = 0; i < 4; i++)
#pragma unroll
        for (int p = 0; p < 4; p++) acc[i][p] = 0ull;
}

__device__ __forceinline__ void acc_row_to_f8(const ull accr[4], float o[8]) {
    unpack2(accr[0], o[0], o[1]);
    unpack2(accr[1], o[2], o[3]);
    unpack2(accr[2], o[4], o[5]);
    unpack2(accr[3], o[6], o[7]);
}

// Load a 128x128 transposed weight (k-major, row-major in g_Wt) into smem
// sW[k][132]. Coalesced LDG.128, conflict-free STS.128 (16B lane stride).
__device__ __forceinline__ void load_w(const float* __restrict__ Wt, float* __restrict__ sW) {
#pragma unroll
    for (int t = 0; t < 16; t++) {
        int f = threadIdx.x + t * 256;          // 0..4095 float4s
        int k = f >> 5, c = (f & 31) << 2;
        *(float4*)(sW + k * 132 + c) = *(const float4*)(Wt + k * 128 + c);
    }
}

// ---------------------------------------------------------------------------
// Kernel 1: transpose the 7 weight matrices once into g_Wt
// ---------------------------------------------------------------------------
__global__ void transpose_weights_kernel(const float* __restrict__ Wz, const float* __restrict__ Uz,
                                         const float* __restrict__ Wr, const float* __restrict__ Ur,
                                         const float* __restrict__ Wh, const float* __restrict__ Uh,
                                         const float* __restrict__ Wp) {
    const float* src = (blockIdx.x == 0) ? Wz : (blockIdx.x == 1) ? Uz :
                       (blockIdx.x == 2) ? Wr : (blockIdx.x == 3) ? Ur :
                       (blockIdx.x == 4) ? Wh : (blockIdx.x == 5) ? Uh : Wp;
    float* dst = g_Wt + blockIdx.x * (ND * ND);
    for (int idx = threadIdx.x; idx < ND * ND; idx += blockDim.x) {
        int j = idx >> 7, k = idx & 127;
        dst[k * ND + j] = src[idx];
    }
}

// ---------------------------------------------------------------------------
// Kernel 2: generic out = X @ W^T (Wt transposed in smem). Used for hp0.
// 768 blocks x 256 threads, 64 rows/block. dynamic smem: sX[64][132]+sW[128][132]
// ---------------------------------------------------------------------------
__global__ void __launch_bounds__(256) xw_kernel(const float* __restrict__ X,
                                                 const float* __restrict__ Wt,
                                                 float* __restrict__ out) {
    extern __shared__ float sm[];
    float* sX = sm;                    // 64*132
    float* sW = sm + 64 * 132;         // 128*132
    int tid = threadIdx.x;
    int tx = tid & 15, ty = tid >> 4;
    int c0 = tx * 4, r0 = ty * 4;
    long base = (long)blockIdx.x * 64;
#pragma unroll
    for (int t = 0; t < 8; t++) {
        int f = tid + t * 256;         // 0..2047 float4s (64x128 floats)
        int r = f >> 5, c = (f & 31) << 2;
        *(float4*)(sX + r * 132 + c) = *(const float4*)(X + (base + r) * ND + c);
    }
    load_w(Wt, sW);
    __syncthreads();
    ull acc[4][4];
    zero_acc(acc);
    mma_block<132>(sX, sW, 128, r0, c0, acc);
#pragma unroll
    for (int i = 0; i < 4; i++) {
        float o[8]; acc_row_to_f8(acc[i], o);
        float* orow = out + (base + r0 + i) * ND;
        *(float4*)(orow + c0)      = make_float4(o[0], o[1], o[2], o[3]);
        *(float4*)(orow + c0 + 64) = make_float4(o[4], o[5], o[6], o[7]);
    }
}

// ---------------------------------------------------------------------------
// Kernel 3: neigh[b] = mask[b] (512x512) @ hp[b] (512x128) + 512*Wp_b
// grid (8 row-tiles, 96 batches), 256 threads, 64x128 tile, K-chunks of 64.
// dynamic smem (51200 B > 48KB static limit): sA[64][68] + sB[64][132]
// ---------------------------------------------------------------------------
__global__ void __launch_bounds__(256) maskgemm_kernel(const float* __restrict__ mask,
                                                       const float* __restrict__ hp,
                                                       const float* __restrict__ bp,
                                                       float* __restrict__ neigh) {
    extern __shared__ float sm[];
    float* sA = sm;                    // 64*68  (mask tile 64x64, pad 68)
    float* sB = sm + 64 * 68;          // 64*132 (hp chunk 64x128, pad 132)
    int b = blockIdx.y;
    int row0g = blockIdx.x * 64;
    int tid = threadIdx.x;
    int tx = tid & 15, ty = tid >> 4;
    int c0 = tx * 4, r0 = ty * 4;
    const float* mrow = mask + ((long)b * NN + row0g) * NN;
    const float* hpb  = hp + (long)b * NN * ND;

    // preload bias into regs (hoisted off the epilogue path)
    float bj[8];
#pragma unroll
    for (int j = 0; j < 8; j++) {
        int col = (j < 4) ? (c0 + j) : (c0 + 60 + j);
        bj[j] = 512.0f * __ldg(bp + col);
    }

    ull acc[4][4];
    zero_acc(acc);
#pragma unroll 1
    for (int k0 = 0; k0 < NN; k0 += 64) {
#pragma unroll
        for (int t = 0; t < 4; t++) {          // 1024 float4s of mask (64x64)
            int f = tid + t * 256;
            int r = f >> 4, kq = (f & 15) << 2;
            *(float4*)(sA + r * 68 + kq) = *(const float4*)(mrow + (long)r * NN + k0 + kq);
        }
#pragma unroll
        for (int t = 0; t < 8; t++) {          // 2048 float4s of hp (64x128)
            int f = tid + t * 256;
            int k = f >> 5, c = (f & 31) << 2;
            *(float4*)(sB + k * 132 + c) = *(const float4*)(hpb + (long)(k0 + k) * ND + c);
        }
        __syncthreads();
        mma_block<68>(sA, sB, 64, r0, c0, acc);
        __syncthreads();
    }
    float* orow = neigh + ((long)b * NN + row0g) * ND;
#pragma unroll
    for (int i = 0; i < 4; i++) {
        float o[8]; acc_row_to_f8(acc[i], o);
#pragma unroll
        for (int j = 0; j < 8; j++) o[j] += bj[j];
        float* r = orow + (long)(r0 + i) * ND;
        *(float4*)(r + c0)      = make_float4(o[0], o[1], o[2], o[3]);
        *(float4*)(r + c0 + 64) = make_float4(o[4], o[5], o[6], o[7]);
    }
}

// ---------------------------------------------------------------------------
// Kernel 4: fused GRU update for 64 rows/block:
//   z = sig(neigh@Wz^T + h@Uz^T + bz), r = sig(neigh@Wr^T + h@Ur^T + br)
//   hhat = tanh(neigh@Wh^T + (r*h)@Uh^T + bh)
//   h' = (1-z)h + z*hhat ;  hp' = h' @ Wp^T   (skipped on last step)
// dynamic smem: sN[64][132] + sH[64][132] + sW[128][132] + 3*128 bias
// ---------------------------------------------------------------------------
__global__ void __launch_bounds__(256) gru_kernel(const float* __restrict__ neigh,
                                                  const float* __restrict__ h_in,
                                                  float* __restrict__ h_out,
                                                  float* __restrict__ hp_out,
                                                  const float* __restrict__ Wt,
                                                  const float* __restrict__ Wz_b, const float* __restrict__ Uz_b,
                                                  const float* __restrict__ Wr_b, const float* __restrict__ Ur_b,
                                                  const float* __restrict__ Wh_b, const float* __restrict__ Uh_b,
                                                  int do_hp) {
    extern __shared__ float sm[];
    float* sN  = sm;                       // 64*132
    float* sH  = sm + 64 * 132;            // 64*132
    float* sW  = sm + 2 * 64 * 132;        // 128*132
    float* sBz = sW + 128 * 132;           // 128
    float* sBr = sBz + 128;
    float* sBh = sBr + 128;
    int tid = threadIdx.x;
    int tx = tid & 15, ty = tid >> 4;
    int c0 = tx * 4, r0 = ty * 4;
    long base = (long)blockIdx.x * 64;

#pragma unroll
    for (int t = 0; t < 8; t++) {
        int f = tid + t * 256;
        int r = f >> 5, c = (f & 31) << 2;
        *(float4*)(sN + r * 132 + c) = *(const float4*)(neigh + (base + r) * ND + c);
        *(float4*)(sH + r * 132 + c) = *(const float4*)(h_in + (base + r) * ND + c);
    }
    if (tid < 128) {
        sBz[tid] = Wz_b[tid] + Uz_b[tid];
        sBr[tid] = Wr_b[tid] + Ur_b[tid];
        sBh[tid] = Wh_b[tid] + Uh_b[tid];
    }
    load_w(Wt + 0 * ND * ND, sW);          // Wz
    __syncthreads();

    ull acc[4][4];
    // ---- z ----
    zero_acc(acc);
    mma_block<132>(sN, sW, 128, r0, c0, acc);
    __syncthreads();
    load_w(Wt + 1 * ND * ND, sW);          // Uz
    __syncthreads();
    mma_block<132>(sH, sW, 128, r0, c0, acc);
    float zf[4][8];
#pragma unroll
    for (int i = 0; i < 4; i++) {
        float o[8]; acc_row_to_f8(acc[i], o);
#pragma unroll
        for (int j = 0; j < 8; j++) {
            int col = (j < 4) ? (c0 + j) : (c0 + 60 + j);
            zf[i][j] = sigmoidf_(o[j] + sBz[col]);
        }
    }
    __syncthreads();
    load_w(Wt + 2 * ND * ND, sW);          // Wr
    __syncthreads();
    // ---- r ----
    zero_acc(acc);
    mma_block<132>(sN, sW, 128, r0, c0, acc);
    __syncthreads();
    load_w(Wt + 3 * ND * ND, sW);          // Ur
    __syncthreads();
    mma_block<132>(sH, sW, 128, r0, c0, acc);
    __syncthreads();                       // all Ur reads of sH and sW done
    load_w(Wt + 4 * ND * ND, sW);          // Wh
    float hreg[4][8];
#pragma unroll
    for (int i = 0; i < 4; i++) {
        float o[8]; acc_row_to_f8(acc[i], o);
#pragma unroll
        for (int j = 0; j < 8; j++) {
            int col = (j < 4) ? (c0 + j) : (c0 + 60 + j);
            float rv = sigmoidf_(o[j] + sBr[col]);
            float hv = sH[(r0 + i) * 132 + col];
            hreg[i][j] = hv;
            sH[(r0 + i) * 132 + col] = rv * hv;   // own (row,col) only — safe
        }
    }
    __syncthreads();
    // ---- h_hat ----
    zero_acc(acc);
    mma_block<132>(sN, sW, 128, r0, c0, acc);
    __syncthreads();
    load_w(Wt + 5 * ND * ND, sW);          // Uh
    __syncthreads();
    mma_block<132>(sH, sW, 128, r0, c0, acc);   // sH holds r*h
    __syncthreads();                       // all Uh reads done
    load_w(Wt + 6 * ND * ND, sW);          // Wp
#pragma unroll
    for (int i = 0; i < 4; i++) {
        float o[8]; acc_row_to_f8(acc[i], o);
        float hn[8];
#pragma unroll
        for (int j = 0; j < 8; j++) {
            int col = (j < 4) ? (c0 + j) : (c0 + 60 + j);
            float hh = tanhf(o[j] + sBh[col]);
            float z  = zf[i][j];
            hn[j] = (1.0f - z) * hreg[i][j] + z * hh;
            sH[(r0 + i) * 132 + col] = hn[j];     // own slot — stage h' for Wp GEMM
        }
        float* orow = h_out + (base + r0 + i) * ND;
        *(float4*)(orow + c0)      = make_float4(hn[0], hn[1], hn[2], hn[3]);
        *(float4*)(orow + c0 + 64) = make_float4(hn[4], hn[5], hn[6], hn[7]);
    }
    __syncthreads();
    if (do_hp) {
        zero_acc(acc);
        mma_block<132>(sH, sW, 128, r0, c0, acc);
#pragma unroll
        for (int i = 0; i < 4; i++) {
            float o[8]; acc_row_to_f8(acc[i], o);
            float* orow = hp_out + (base + r0 + i) * ND;
            *(float4*)(orow + c0)      = make_float4(o[0], o[1], o[2], o[3]);
            *(float4*)(orow + c0 + 64) = make_float4(o[4], o[5], o[6], o[7]);
        }
    }
}

// ---------------------------------------------------------------------------
extern "C" void kernel_launch(void* const* d_in, const int* in_sizes, int n_in,
                              void* d_out, int out_size) {
    const float* init_node = (const float*)d_in[0];
    const float* mask      = (const float*)d_in[1];
    // d_in[2] = n_steps (fixed at 5 by the problem definition)
    const float* Wp_w = (const float*)d_in[3];
    const float* Wp_b = (const float*)d_in[4];
    const float* Wz_w = (const float*)d_in[5];
    const float* Wz_b = (const float*)d_in[6];
    const float* Uz_w = (const float*)d_in[7];
    const float* Uz_b = (const float*)d_in[8];
    const float* Wr_w = (const float*)d_in[9];
    const float* Wr_b = (const float*)d_in[10];
    const float* Ur_w = (const float*)d_in[11];
    const float* Ur_b = (const float*)d_in[12];
    const float* Wh_w = (const float*)d_in[13];
    const float* Wh_b = (const float*)d_in[14];
    const float* Uh_w = (const float*)d_in[15];
    const float* Uh_b = (const float*)d_in[16];
    float* hout = (float*)d_out;

    float *g_hp_p, *g_neigh_p, *g_Wt_p;
    cudaGetSymbolAddress((void**)&g_hp_p, g_hp);
    cudaGetSymbolAddress((void**)&g_neigh_p, g_neigh);
    cudaGetSymbolAddress((void**)&g_Wt_p, g_Wt);

    const int GRU_SMEM = (2 * 64 * 132 + 128 * 132 + 3 * 128) * sizeof(float);  // 136704
    const int XW_SMEM  = (64 * 132 + 128 * 132) * sizeof(float);                // 101376
    const int MG_SMEM  = (64 * 68 + 64 * 132) * sizeof(float);                  // 51200
    cudaFuncSetAttribute(gru_kernel,      cudaFuncAttributeMaxDynamicSharedMemorySize, GRU_SMEM);
    cudaFuncSetAttribute(xw_kernel,       cudaFuncAttributeMaxDynamicSharedMemorySize, XW_SMEM);
    cudaFuncSetAttribute(maskgemm_kernel, cudaFuncAttributeMaxDynamicSharedMemorySize, MG_SMEM);

    transpose_weights_kernel<<<7, 256>>>(Wz_w, Uz_w, Wr_w, Ur_w, Wh_w, Uh_w, Wp_w);
    xw_kernel<<<NROWS / 64, 256, XW_SMEM>>>(init_node, g_Wt_p + 6 * ND * ND, g_hp_p);

    for (int s = 0; s < NSTEPS; s++) {
        maskgemm_kernel<<<dim3(NN / 64, NB), 256, MG_SMEM>>>(mask, g_hp_p, Wp_b, g_neigh_p);
        gru_kernel<<<NROWS / 64, 256, GRU_SMEM>>>(
            g_neigh_p, (s == 0) ? init_node : hout, hout, g_hp_p,
            g_Wt_p, Wz_b, Uz_b, Wr_b, Ur_b, Wh_b, Uh_b, (s < NSTEPS - 1) ? 1 : 0);
    }
}

// round 7
// speedup vs baseline: 1.0009x; 1.0009x over previous
#include <cuda_runtime.h>
#include <cstdint>

// Problem constants (fixed by setup_inputs): B=96, N_NODE=512, D=128, n_steps=5
#define NB 96
#define NN 512
#define ND 128
#define NROWS (NB * NN)            // 49152
#define NSTEPS 5

// Scratch (allocation-free rule: __device__ globals)
__device__ float g_hp[NROWS * ND];      // h @ Wp^T  [node][feat]
__device__ float g_neigh[NROWS * ND];   // mask @ hp + n*bp
__device__ float g_Wt[7 * ND * ND];     // transposed weights: [k][j] = W[j][k]
// order: 0=Wz 1=Uz 2=Wr 3=Ur 4=Wh 5=Uh 6=Wp

typedef unsigned long long ull;

__device__ __forceinline__ ull pack2(float lo, float hi) {
    ull r; asm("mov.b64 %0, {%1,%2};" : "=l"(r) : "f"(lo), "f"(hi)); return r;
}
__device__ __forceinline__ void fma2(ull& d, ull a, ull b) {
    asm("fma.rn.f32x2 %0, %1, %2, %0;" : "+l"(d) : "l"(a), "l"(b));
}
__device__ __forceinline__ void unpack2(ull v, float& lo, float& hi) {
    asm("mov.b64 {%0,%1}, %2;" : "=f"(lo), "=f"(hi) : "l"(v));
}
__device__ __forceinline__ float sigmoidf_(float x) { return 1.0f / (1.0f + __expf(-x)); }
__device__ __forceinline__ uint32_t s2u(const void* p) {
    uint32_t a;
    asm("{ .reg .u64 t; cvta.to.shared.u64 t, %1; cvt.u32.u64 %0, t; }" : "=r"(a) : "l"(p));
    return a;
}
__device__ __forceinline__ void cp16(float* dst, const float* src) {
    asm volatile("cp.async.cg.shared.global [%0], [%1], 16;" :: "r"(s2u(dst)), "l"(src));
}
#define CP_COMMIT() asm volatile("cp.async.commit_group;")
#define CP_WAIT(n)  asm volatile("cp.async.wait_group %0;" :: "n"(n))

// ---------------------------------------------------------------------------
// Core micro-kernel (identical to R3-passing): 64-row x 128-col tile, 256 thr
// (16x16), per-thread 4 rows x 8 cols (c0..c0+3, c0+64..c0+67; c0 = 4*tx).
// sX: [rows][LDX] (k contig). sW: [K][132] (j contig). acc = packed f32x2.
// ---------------------------------------------------------------------------
template <int LDX>
__device__ __forceinline__ void mma_block(const float* __restrict__ sX,
                                          const float* __restrict__ sW,
                                          int K, int r0, int c0, ull acc[4][4]) {
#pragma unroll 2
    for (int k = 0; k < K; k += 4) {
        float4 a0 = *(const float4*)(sX + (r0 + 0) * LDX + k);
        float4 a1 = *(const float4*)(sX + (r0 + 1) * LDX + k);
        float4 a2 = *(const float4*)(sX + (r0 + 2) * LDX + k);
        float4 a3 = *(const float4*)(sX + (r0 + 3) * LDX + k);
#pragma unroll
        for (int kk = 0; kk < 4; kk++) {
            const float* wr = sW + (k + kk) * 132;
            float4 w0 = *(const float4*)(wr + c0);
            float4 w1 = *(const float4*)(wr + c0 + 64);
            ull wp0 = pack2(w0.x, w0.y), wp1 = pack2(w0.z, w0.w);
            ull wp2 = pack2(w1.x, w1.y), wp3 = pack2(w1.z, w1.w);
            float e0 = (kk == 0) ? a0.x : (kk == 1) ? a0.y : (kk == 2) ? a0.z : a0.w;
            float e1 = (kk == 0) ? a1.x : (kk == 1) ? a1.y : (kk == 2) ? a1.z : a1.w;
            float e2 = (kk == 0) ? a2.x : (kk == 1) ? a2.y : (kk == 2) ? a2.z : a2.w;
            float e3 = (kk == 0) ? a3.x : (kk == 1) ? a3.y : (kk == 2) ? a3.z : a3.w;
            ull ap0 = pack2(e0, e0), ap1 = pack2(e1, e1);
            ull ap2 = pack2(e2, e2), ap3 = pack2(e3, e3);
            fma2(acc[0][0], ap0, wp0); fma2(acc[0][1], ap0, wp1);
            fma2(acc[0][2], ap0, wp2); fma2(acc[0][3], ap0, wp3);
            fma2(acc[1][0], ap1, wp0); fma2(acc[1][1], ap1, wp1);
            fma2(acc[1][2], ap1, wp2); fma2(acc[1][3], ap1, wp3);
            fma2(acc[2][0], ap2, wp0); fma2(acc[2][1], ap2, wp1);
            fma2(acc[2][2], ap2, wp2); fma2(acc[2][3], ap2, wp3);
            fma2(acc[3][0], ap3, wp0); fma2(acc[3][1], ap3, wp1);
            fma2(acc[3][2], ap3, wp2); fma2(acc[3][3], ap3, wp3);
        }
    }
}

__device__ __forceinline__ void zero_acc(ull acc[4][4]) {
#pragma unroll
    for (int i = 0; i < 4; i++)
#pragma unroll
        for (int p = 0; p < 4; p++) acc[i][p] = 0ull;
}
__device__ __forceinline__ void acc_row_to_f8(const ull accr[4], float o[8]) {
    unpack2(accr[0], o[0], o[1]);
    unpack2(accr[1], o[2], o[3]);
    unpack2(accr[2], o[4], o[5]);
    unpack2(accr[3], o[6], o[7]);
}

// Async-load a 128x128 transposed weight into smem [K][132] and commit a group.
__device__ __forceinline__ void cpw(float* __restrict__ dst, const float* __restrict__ Wt) {
#pragma unroll
    for (int t = 0; t < 16; t++) {
        int f = threadIdx.x + t * 256;          // 0..4095 float4s
        int k = f >> 5, c = (f & 31) << 2;
        cp16(dst + k * 132 + c, Wt + k * 128 + c);
    }
    CP_COMMIT();
}
// Blocking weight load (used by xw_kernel only)
__device__ __forceinline__ void load_w(const float* __restrict__ Wt, float* __restrict__ sW) {
#pragma unroll
    for (int t = 0; t < 16; t++) {
        int f = threadIdx.x + t * 256;
        int k = f >> 5, c = (f & 31) << 2;
        *(float4*)(sW + k * 132 + c) = *(const float4*)(Wt + k * 128 + c);
    }
}

// ---------------------------------------------------------------------------
// Kernel 1: transpose the 7 weight matrices once into g_Wt
// ---------------------------------------------------------------------------
__global__ void transpose_weights_kernel(const float* __restrict__ Wz, const float* __restrict__ Uz,
                                         const float* __restrict__ Wr, const float* __restrict__ Ur,
                                         const float* __restrict__ Wh, const float* __restrict__ Uh,
                                         const float* __restrict__ Wp) {
    const float* src = (blockIdx.x == 0) ? Wz : (blockIdx.x == 1) ? Uz :
                       (blockIdx.x == 2) ? Wr : (blockIdx.x == 3) ? Ur :
                       (blockIdx.x == 4) ? Wh : (blockIdx.x == 5) ? Uh : Wp;
    float* dst = g_Wt + blockIdx.x * (ND * ND);
    for (int idx = threadIdx.x; idx < ND * ND; idx += blockDim.x) {
        int j = idx >> 7, k = idx & 127;
        dst[k * ND + j] = src[idx];
    }
}

// ---------------------------------------------------------------------------
// Kernel 2: hp0 = init_node @ Wp^T  (one-time)
// ---------------------------------------------------------------------------
#define XW_SMEM ((64 * 132 + 128 * 132) * 4)
__global__ void __launch_bounds__(256) xw_kernel(const float* __restrict__ X,
                                                 const float* __restrict__ Wt,
                                                 float* __restrict__ out) {
    extern __shared__ float sm[];
    float* sX = sm;
    float* sW = sm + 64 * 132;
    int tid = threadIdx.x;
    int tx = tid & 15, ty = tid >> 4;
    int c0 = tx * 4, r0 = ty * 4;
    long base = (long)blockIdx.x * 64;
#pragma unroll
    for (int t = 0; t < 8; t++) {
        int f = tid + t * 256;
        int r = f >> 5, c = (f & 31) << 2;
        *(float4*)(sX + r * 132 + c) = *(const float4*)(X + (base + r) * ND + c);
    }
    load_w(Wt, sW);
    __syncthreads();
    ull acc[4][4];
    zero_acc(acc);
    mma_block<132>(sX, sW, 128, r0, c0, acc);
#pragma unroll
    for (int i = 0; i < 4; i++) {
        float o[8]; acc_row_to_f8(acc[i], o);
        float* orow = out + (base + r0 + i) * ND;
        *(float4*)(orow + c0)      = make_float4(o[0], o[1], o[2], o[3]);
        *(float4*)(orow + c0 + 64) = make_float4(o[4], o[5], o[6], o[7]);
    }
}

// ---------------------------------------------------------------------------
// Kernel 3: neigh[b] = mask[b] @ hp[b] + 512*Wp_b — cp.async double-buffered
// K-chunks of 64. grid (8 x 96), 256 thr.
// ---------------------------------------------------------------------------
#define MG_SMEM ((2 * 64 * 68 + 2 * 64 * 132) * 4)   // 102400
__global__ void __launch_bounds__(256) maskgemm_kernel(const float* __restrict__ mask,
                                                       const float* __restrict__ hp,
                                                       const float* __restrict__ bp,
                                                       float* __restrict__ neigh) {
    extern __shared__ float sm[];
    float* sA[2] = { sm, sm + 64 * 68 };
    float* sB[2] = { sm + 2 * 64 * 68, sm + 2 * 64 * 68 + 64 * 132 };
    int b = blockIdx.y;
    int row0g = blockIdx.x * 64;
    int tid = threadIdx.x;
    int tx = tid & 15, ty = tid >> 4;
    int c0 = tx * 4, r0 = ty * 4;
    const float* mrow = mask + ((long)b * NN + row0g) * NN;
    const float* hpb  = hp + (long)b * NN * ND;

    float bj[8];
#pragma unroll
    for (int j = 0; j < 8; j++) {
        int col = (j < 4) ? (c0 + j) : (c0 + 60 + j);
        bj[j] = 512.0f * __ldg(bp + col);
    }

    auto loadChunk = [&](int buf, int k0) {
#pragma unroll
        for (int t = 0; t < 4; t++) {          // mask 64x64: 1024 f4
            int f = tid + t * 256;
            int r = f >> 4, kq = (f & 15) << 2;
            cp16(sA[buf] + r * 68 + kq, mrow + (long)r * NN + k0 + kq);
        }
#pragma unroll
        for (int t = 0; t < 8; t++) {          // hp 64x128: 2048 f4
            int f = tid + t * 256;
            int k = f >> 5, c = (f & 31) << 2;
            cp16(sB[buf] + k * 132 + c, hpb + (long)(k0 + k) * ND + c);
        }
        CP_COMMIT();
    };

    ull acc[4][4];
    zero_acc(acc);
    loadChunk(0, 0);
#pragma unroll 1
    for (int c = 0; c < 8; c++) {
        if (c < 7) { loadChunk((c + 1) & 1, (c + 1) * 64); CP_WAIT(1); }
        else       { CP_WAIT(0); }
        __syncthreads();
        mma_block<68>(sA[c & 1], sB[c & 1], 64, r0, c0, acc);
        __syncthreads();
    }
    float* orow = neigh + ((long)b * NN + row0g) * ND;
#pragma unroll
    for (int i = 0; i < 4; i++) {
        float o[8]; acc_row_to_f8(acc[i], o);
#pragma unroll
        for (int j = 0; j < 8; j++) o[j] += bj[j];
        float* r = orow + (long)(r0 + i) * ND;
        *(float4*)(r + c0)      = make_float4(o[0], o[1], o[2], o[3]);
        *(float4*)(r + c0 + 64) = make_float4(o[4], o[5], o[6], o[7]);
    }
}

// ---------------------------------------------------------------------------
// Kernel 4: fused GRU, weights prefetched via cp.async into Wa/Wb ping-pong.
// smem: sN[64][132] + sH[64][132] + Wa[128][132] + Wb[128][132] + 3*128 bias
// ---------------------------------------------------------------------------
#define GRU_SMEM ((2 * 64 * 132 + 2 * 128 * 132 + 3 * 128) * 4)   // 204288
__global__ void __launch_bounds__(256) gru_kernel(const float* __restrict__ neigh,
                                                  const float* __restrict__ h_in,
                                                  float* __restrict__ h_out,
                                                  float* __restrict__ hp_out,
                                                  const float* __restrict__ Wt,
                                                  const float* __restrict__ Wz_b, const float* __restrict__ Uz_b,
                                                  const float* __restrict__ Wr_b, const float* __restrict__ Ur_b,
                                                  const float* __restrict__ Wh_b, const float* __restrict__ Uh_b,
                                                  int do_hp) {
    extern __shared__ float sm[];
    float* sN  = sm;                       // 64*132
    float* sH  = sm + 64 * 132;            // 64*132 (h, then r*h, then h')
    float* Wa  = sm + 2 * 64 * 132;        // 128*132
    float* Wb  = Wa + 128 * 132;           // 128*132
    float* sBz = Wb + 128 * 132;           // 128
    float* sBr = sBz + 128;
    float* sBh = sBr + 128;
    int tid = threadIdx.x;
    int tx = tid & 15, ty = tid >> 4;
    int c0 = tx * 4, r0 = ty * 4;
    long base = (long)blockIdx.x * 64;

    // GA = {sN, sH, Wz}; GB = {Uz}
#pragma unroll
    for (int t = 0; t < 8; t++) {
        int f = tid + t * 256;
        int r = f >> 5, c = (f & 31) << 2;
        cp16(sN + r * 132 + c, neigh + (base + r) * ND + c);
        cp16(sH + r * 132 + c, h_in + (base + r) * ND + c);
    }
    cpw(Wa, Wt + 0 * ND * ND);             // commits GA
    cpw(Wb, Wt + 1 * ND * ND);             // GB
    if (tid < 128) {                        // overlaps the async loads
        sBz[tid] = Wz_b[tid] + Uz_b[tid];
        sBr[tid] = Wr_b[tid] + Ur_b[tid];
        sBh[tid] = Wh_b[tid] + Uh_b[tid];
    }

    ull acc[4][4];
    CP_WAIT(1); __syncthreads();           // GA: sN,sH,Wz ready (bias stores also fenced)
    zero_acc(acc);
    mma_block<132>(sN, Wa, 128, r0, c0, acc);           // z1
    __syncthreads(); cpw(Wa, Wt + 2 * ND * ND);         // GC = Wr
    CP_WAIT(1); __syncthreads();           // GB: Uz
    mma_block<132>(sH, Wb, 128, r0, c0, acc);           // z2
    float zf[4][8];
#pragma unroll
    for (int i = 0; i < 4; i++) {
        float o[8]; acc_row_to_f8(acc[i], o);
#pragma unroll
        for (int j = 0; j < 8; j++) {
            int col = (j < 4) ? (c0 + j) : (c0 + 60 + j);
            zf[i][j] = sigmoidf_(o[j] + sBz[col]);
        }
    }
    __syncthreads(); cpw(Wb, Wt + 3 * ND * ND);         // GD = Ur
    CP_WAIT(1); __syncthreads();           // GC: Wr
    zero_acc(acc);
    mma_block<132>(sN, Wa, 128, r0, c0, acc);           // r1
    __syncthreads(); cpw(Wa, Wt + 4 * ND * ND);         // GE = Wh
    CP_WAIT(1); __syncthreads();           // GD: Ur
    mma_block<132>(sH, Wb, 128, r0, c0, acc);           // r2
    __syncthreads();                       // all r2 reads of sH done
    cpw(Wb, Wt + 5 * ND * ND);                          // GF = Uh
    float hreg[4][8];
#pragma unroll
    for (int i = 0; i < 4; i++) {          // rh epilogue (overlaps Uh load)
        float o[8]; acc_row_to_f8(acc[i], o);
#pragma unroll
        for (int j = 0; j < 8; j++) {
            int col = (j < 4) ? (c0 + j) : (c0 + 60 + j);
            float rv = sigmoidf_(o[j] + sBr[col]);
            float hv = sH[(r0 + i) * 132 + col];
            hreg[i][j] = hv;
            sH[(r0 + i) * 132 + col] = rv * hv;         // own slot only
        }
    }
    CP_WAIT(1); __syncthreads();           // GE: Wh; rh visible
    zero_acc(acc);
    mma_block<132>(sN, Wa, 128, r0, c0, acc);           // h1 (last read of sN)
    __syncthreads(); cpw(Wa, Wt + 6 * ND * ND);         // GG = Wp
    CP_WAIT(1); __syncthreads();           // GF: Uh
    mma_block<132>(sH, Wb, 128, r0, c0, acc);           // h2 (sH = r*h)
    __syncthreads();                       // all h2 reads of sH done
#pragma unroll
    for (int i = 0; i < 4; i++) {          // combine epilogue
        float o[8]; acc_row_to_f8(acc[i], o);
        float hn[8];
#pragma unroll
        for (int j = 0; j < 8; j++) {
            int col = (j < 4) ? (c0 + j) : (c0 + 60 + j);
            float hh = tanhf(o[j] + sBh[col]);
            float z  = zf[i][j];
            hn[j] = (1.0f - z) * hreg[i][j] + z * hh;
            sH[(r0 + i) * 132 + col] = hn[j];           // stage h' (own slot)
        }
        float* orow = h_out + (base + r0 + i) * ND;
        *(float4*)(orow + c0)      = make_float4(hn[0], hn[1], hn[2], hn[3]);
        *(float4*)(orow + c0 + 64) = make_float4(hn[4], hn[5], hn[6], hn[7]);
    }
    CP_WAIT(0); __syncthreads();           // GG: Wp; h' visible
    if (do_hp) {
        zero_acc(acc);
        mma_block<132>(sH, Wa, 128, r0, c0, acc);       // hp = h' @ Wp^T
#pragma unroll
        for (int i = 0; i < 4; i++) {
            float o[8]; acc_row_to_f8(acc[i], o);
            float* orow = hp_out + (base + r0 + i) * ND;
            *(float4*)(orow + c0)      = make_float4(o[0], o[1], o[2], o[3]);
            *(float4*)(orow + c0 + 64) = make_float4(o[4], o[5], o[6], o[7]);
        }
    }
}

// ---------------------------------------------------------------------------
extern "C" void kernel_launch(void* const* d_in, const int* in_sizes, int n_in,
                              void* d_out, int out_size) {
    const float* init_node = (const float*)d_in[0];
    const float* mask      = (const float*)d_in[1];
    // d_in[2] = n_steps (fixed at 5 by the problem definition)
    const float* Wp_w = (const float*)d_in[3];
    const float* Wp_b = (const float*)d_in[4];
    const float* Wz_w = (const float*)d_in[5];
    const float* Wz_b = (const float*)d_in[6];
    const float* Uz_w = (const float*)d_in[7];
    const float* Uz_b = (const float*)d_in[8];
    const float* Wr_w = (const float*)d_in[9];
    const float* Wr_b = (const float*)d_in[10];
    const float* Ur_w = (const float*)d_in[11];
    const float* Ur_b = (const float*)d_in[12];
    const float* Wh_w = (const float*)d_in[13];
    const float* Wh_b = (const float*)d_in[14];
    const float* Uh_w = (const float*)d_in[15];
    const float* Uh_b = (const float*)d_in[16];
    float* hout = (float*)d_out;

    float *g_hp_p, *g_neigh_p, *g_Wt_p;
    cudaGetSymbolAddress((void**)&g_hp_p, g_hp);
    cudaGetSymbolAddress((void**)&g_neigh_p, g_neigh);
    cudaGetSymbolAddress((void**)&g_Wt_p, g_Wt);

    cudaFuncSetAttribute(gru_kernel,      cudaFuncAttributeMaxDynamicSharedMemorySize, GRU_SMEM);
    cudaFuncSetAttribute(xw_kernel,       cudaFuncAttributeMaxDynamicSharedMemorySize, XW_SMEM);
    cudaFuncSetAttribute(maskgemm_kernel, cudaFuncAttributeMaxDynamicSharedMemorySize, MG_SMEM);

    transpose_weights_kernel<<<7, 256>>>(Wz_w, Uz_w, Wr_w, Ur_w, Wh_w, Uh_w, Wp_w);
    xw_kernel<<<NROWS / 64, 256, XW_SMEM>>>(init_node, g_Wt_p + 6 * ND * ND, g_hp_p);

    for (int s = 0; s < NSTEPS; s++) {
        maskgemm_kernel<<<dim3(NN / 64, NB), 256, MG_SMEM>>>(mask, g_hp_p, Wp_b, g_neigh_p);
        gru_kernel<<<NROWS / 64, 256, GRU_SMEM>>>(
            g_neigh_p, (s == 0) ? init_node : hout, hout, g_hp_p,
            g_Wt_p, Wz_b, Uz_b, Wr_b, Ur_b, Wh_b, Uh_b, (s < NSTEPS - 1) ? 1 : 0);
    }
}

// round 8
// speedup vs baseline: 1.0313x; 1.0304x over previous
#include <cuda_runtime.h>
#include <cstdint>

// Problem constants (fixed by setup_inputs): B=96, N_NODE=512, D=128, n_steps=5
#define NB 96
#define NN 512
#define ND 128
#define NROWS (NB * NN)            // 49152
#define NSTEPS 5

// Scratch (allocation-free rule: __device__ globals)
__device__ float g_hp[NROWS * ND];      // h @ Wp^T  [node][feat]
__device__ float g_neigh[NROWS * ND];   // mask @ hp + 512*bp
__device__ float g_z[NROWS * ND];       // z-gate spill (thread-local roundtrip)
__device__ float g_Wt[7 * ND * ND];     // transposed weights: [k][j] = W[j][k]
// order: 0=Wz 1=Uz 2=Wr 3=Ur 4=Wh 5=Uh 6=Wp

typedef unsigned long long ull;

__device__ __forceinline__ ull pack2(float lo, float hi) {
    ull r; asm("mov.b64 %0, {%1,%2};" : "=l"(r) : "f"(lo), "f"(hi)); return r;
}
__device__ __forceinline__ void fma2(ull& d, ull a, ull b) {
    asm("fma.rn.f32x2 %0, %1, %2, %0;" : "+l"(d) : "l"(a), "l"(b));
}
__device__ __forceinline__ void unpack2(ull v, float& lo, float& hi) {
    asm("mov.b64 {%0,%1}, %2;" : "=f"(lo), "=f"(hi) : "l"(v));
}
__device__ __forceinline__ float sigmoidf_(float x) { return 1.0f / (1.0f + __expf(-x)); }
__device__ __forceinline__ uint32_t s2u(const void* p) {
    uint32_t a;
    asm("{ .reg .u64 t; cvta.to.shared.u64 t, %1; cvt.u32.u64 %0, t; }" : "=r"(a) : "l"(p));
    return a;
}
__device__ __forceinline__ void cp16(float* dst, const float* src) {
    asm volatile("cp.async.cg.shared.global [%0], [%1], 16;" :: "r"(s2u(dst)), "l"(src));
}
#define CP_COMMIT() asm volatile("cp.async.commit_group;")
#define CP_WAIT(n)  asm volatile("cp.async.wait_group %0;" :: "n"(n))

// ---------------------------------------------------------------------------
// r8c8 micro-kernel over a 64-k slab: thread computes 8 rows x 8 cols.
// 256 threads = 16x16 (tx,ty): rows r0=8*ty..+7; cols c0=4*tx..+3, c0+64..+67.
// sX: [128 rows][LDA] (k contig), k index = kbase + k.  sW: [64 k][132].
// A-row loads broadcast (2 addrs/warp); W loads 16B-lane-stride conflict-free.
// ---------------------------------------------------------------------------
template <int LDA>
__device__ __forceinline__ void mma_half(const float* __restrict__ sX,
                                         const float* __restrict__ sW,
                                         int kbase, int r0, int c0, ull acc[8][4]) {
#pragma unroll 2
    for (int k = 0; k < 64; k += 4) {
        float4 a[8];
#pragma unroll
        for (int i = 0; i < 8; i++)
            a[i] = *(const float4*)(sX + (r0 + i) * LDA + kbase + k);
#pragma unroll
        for (int kk = 0; kk < 4; kk++) {
            const float* wr = sW + (k + kk) * 132;
            float4 w0 = *(const float4*)(wr + c0);
            float4 w1 = *(const float4*)(wr + c0 + 64);
            ull wp0 = pack2(w0.x, w0.y), wp1 = pack2(w0.z, w0.w);
            ull wp2 = pack2(w1.x, w1.y), wp3 = pack2(w1.z, w1.w);
#pragma unroll
            for (int i = 0; i < 8; i++) {
                float e = (kk == 0) ? a[i].x : (kk == 1) ? a[i].y : (kk == 2) ? a[i].z : a[i].w;
                ull ap = pack2(e, e);
                fma2(acc[i][0], ap, wp0); fma2(acc[i][1], ap, wp1);
                fma2(acc[i][2], ap, wp2); fma2(acc[i][3], ap, wp3);
            }
        }
    }
}

__device__ __forceinline__ void zero_acc8(ull acc[8][4]) {
#pragma unroll
    for (int i = 0; i < 8; i++)
#pragma unroll
        for (int p = 0; p < 4; p++) acc[i][p] = 0ull;
}
__device__ __forceinline__ void row_to_f8(const ull a[4], float o[8]) {
    unpack2(a[0], o[0], o[1]); unpack2(a[1], o[2], o[3]);
    unpack2(a[2], o[4], o[5]); unpack2(a[3], o[6], o[7]);
}
__device__ __forceinline__ int colof(int c0, int j) { return (j < 4) ? (c0 + j) : (c0 + 60 + j); }

// Async-load one 64x128 weight half into smem [64][132]; commits a group.
__device__ __forceinline__ void cp_half(float* __restrict__ dst, const float* __restrict__ src) {
#pragma unroll
    for (int t = 0; t < 8; t++) {
        int f = threadIdx.x + t * 256;          // 0..2047 float4s
        int k = f >> 5, c = (f & 31) << 2;
        cp16(dst + k * 132 + c, src + k * 128 + c);
    }
    CP_COMMIT();
}

// ---------------------------------------------------------------------------
// Kernel 1: transpose the 7 weight matrices once into g_Wt
// ---------------------------------------------------------------------------
__global__ void transpose_weights_kernel(const float* __restrict__ Wz, const float* __restrict__ Uz,
                                         const float* __restrict__ Wr, const float* __restrict__ Ur,
                                         const float* __restrict__ Wh, const float* __restrict__ Uh,
                                         const float* __restrict__ Wp) {
    const float* src = (blockIdx.x == 0) ? Wz : (blockIdx.x == 1) ? Uz :
                       (blockIdx.x == 2) ? Wr : (blockIdx.x == 3) ? Ur :
                       (blockIdx.x == 4) ? Wh : (blockIdx.x == 5) ? Uh : Wp;
    float* dst = g_Wt + blockIdx.x * (ND * ND);
    for (int idx = threadIdx.x; idx < ND * ND; idx += blockDim.x) {
        int j = idx >> 7, k = idx & 127;
        dst[k * ND + j] = src[idx];
    }
}

// ---------------------------------------------------------------------------
// Kernel 2: hp0 = init_node @ Wp^T  (one-time). 128-row tiles, r8c8.
// ---------------------------------------------------------------------------
#define XW_SMEM ((128 * 132 * 2) * 4)   // 135168
__global__ void __launch_bounds__(256) xw_kernel(const float* __restrict__ X,
                                                 const float* __restrict__ Wt,
                                                 float* __restrict__ out) {
    extern __shared__ float sm[];
    float* sX = sm;                 // [128][132]
    float* sW = sm + 128 * 132;     // [128][132]
    int tid = threadIdx.x;
    int tx = tid & 15, ty = tid >> 4;
    int c0 = tx * 4, r0 = ty * 8;
    long base = (long)blockIdx.x * 128;
#pragma unroll
    for (int t = 0; t < 16; t++) {
        int f = tid + t * 256;      // 0..4095 f4
        int r = f >> 5, c = (f & 31) << 2;
        *(float4*)(sX + r * 132 + c) = *(const float4*)(X + (base + r) * ND + c);
        *(float4*)(sW + r * 132 + c) = *(const float4*)(Wt + r * 128 + c);
    }
    __syncthreads();
    ull acc[8][4];
    zero_acc8(acc);
    mma_half<132>(sX, sW, 0, r0, c0, acc);
    mma_half<132>(sX, sW + 64 * 132, 64, r0, c0, acc);
#pragma unroll
    for (int i = 0; i < 8; i++) {
        float o[8]; row_to_f8(acc[i], o);
        float* orow = out + (base + r0 + i) * ND;
        *(float4*)(orow + c0)      = make_float4(o[0], o[1], o[2], o[3]);
        *(float4*)(orow + c0 + 64) = make_float4(o[4], o[5], o[6], o[7]);
    }
}

// ---------------------------------------------------------------------------
// Kernel 3: neigh[b] = mask[b] @ hp[b] + 512*Wp_b. 128x128 tile, r8c8,
// K=512 in 8 chunks of 64, cp.async double-buffered. grid (4, 96).
// ---------------------------------------------------------------------------
#define MG_SMEM ((2 * 128 * 68 + 2 * 64 * 132) * 4)   // 137216
__global__ void __launch_bounds__(256) maskgemm_kernel(const float* __restrict__ mask,
                                                       const float* __restrict__ hp,
                                                       const float* __restrict__ bp,
                                                       float* __restrict__ neigh) {
    extern __shared__ float sm[];
    float* sA[2] = { sm, sm + 128 * 68 };
    float* sB[2] = { sm + 2 * 128 * 68, sm + 2 * 128 * 68 + 64 * 132 };
    int b = blockIdx.y;
    int row0g = blockIdx.x * 128;
    int tid = threadIdx.x;
    int tx = tid & 15, ty = tid >> 4;
    int c0 = tx * 4, r0 = ty * 8;
    const float* mrow = mask + ((long)b * NN + row0g) * NN;
    const float* hpb  = hp + (long)b * NN * ND;

    float bj[8];
#pragma unroll
    for (int j = 0; j < 8; j++) bj[j] = 512.0f * __ldg(bp + colof(c0, j));

    auto loadChunk = [&](int buf, int k0) {
#pragma unroll
        for (int t = 0; t < 8; t++) {          // mask 128x64: 2048 f4
            int f = tid + t * 256;
            int r = f >> 4, kq = (f & 15) << 2;
            cp16(sA[buf] + r * 68 + kq, mrow + (long)r * NN + k0 + kq);
        }
#pragma unroll
        for (int t = 0; t < 8; t++) {          // hp 64x128: 2048 f4
            int f = tid + t * 256;
            int k = f >> 5, c = (f & 31) << 2;
            cp16(sB[buf] + k * 132 + c, hpb + (long)(k0 + k) * ND + c);
        }
        CP_COMMIT();
    };

    ull acc[8][4];
    zero_acc8(acc);
    loadChunk(0, 0);
#pragma unroll 1
    for (int c = 0; c < 8; c++) {
        if (c < 7) { loadChunk((c + 1) & 1, (c + 1) * 64); CP_WAIT(1); }
        else       { CP_WAIT(0); }
        __syncthreads();
        mma_half<68>(sA[c & 1], sB[c & 1], 0, r0, c0, acc);
        __syncthreads();
    }
    float* orow = neigh + ((long)b * NN + row0g) * ND;
#pragma unroll
    for (int i = 0; i < 8; i++) {
        float o[8]; row_to_f8(acc[i], o);
#pragma unroll
        for (int j = 0; j < 8; j++) o[j] += bj[j];
        float* r = orow + (long)(r0 + i) * ND;
        *(float4*)(r + c0)      = make_float4(o[0], o[1], o[2], o[3]);
        *(float4*)(r + c0 + 64) = make_float4(o[4], o[5], o[6], o[7]);
    }
}

// ---------------------------------------------------------------------------
// Kernel 4: fused GRU, 128 nodes/CTA, r8c8, half-weight ping-pong pipeline.
// smem: sN[128][132] (neigh -> rh -> h'), sH[128][132] (h), wb[2][64][132],
//       3x128 bias. Weight halves streamed: Wz0,Wz1,Uz0,Uz1,Wr0..Wp1 (14).
// z gate round-trips through g_z (thread re-reads only its own cells).
// ---------------------------------------------------------------------------
#define GRU_SMEM ((2 * 128 * 132 + 2 * 64 * 132 + 3 * 128) * 4)   // 204288
__global__ void __launch_bounds__(256) gru_kernel(const float* __restrict__ neigh,
                                                  const float* __restrict__ h_in,
                                                  float* __restrict__ h_out,
                                                  float* __restrict__ hp_out,
                                                  float* __restrict__ zbuf,
                                                  const float* __restrict__ Wt,
                                                  const float* __restrict__ Wz_b, const float* __restrict__ Uz_b,
                                                  const float* __restrict__ Wr_b, const float* __restrict__ Ur_b,
                                                  const float* __restrict__ Wh_b, const float* __restrict__ Uh_b,
                                                  int do_hp) {
    extern __shared__ float sm[];
    float* sN  = sm;                       // 128*132
    float* sH  = sm + 128 * 132;           // 128*132
    float* wb0 = sm + 2 * 128 * 132;       // 64*132
    float* wb1 = wb0 + 64 * 132;           // 64*132
    float* sBz = wb1 + 64 * 132;           // 128
    float* sBr = sBz + 128;
    float* sBh = sBr + 128;
    float* wb[2] = { wb0, wb1 };
    int tid = threadIdx.x;
    int tx = tid & 15, ty = tid >> 4;
    int c0 = tx * 4, r0 = ty * 8;
    long base = (long)blockIdx.x * 128;

    // G0 = {sN, sH, half0=Wz0}; G1 = {half1=Wz1}
#pragma unroll
    for (int t = 0; t < 16; t++) {
        int f = tid + t * 256;
        int r = f >> 5, c = (f & 31) << 2;
        cp16(sN + r * 132 + c, neigh + (base + r) * ND + c);
        cp16(sH + r * 132 + c, h_in + (base + r) * ND + c);
    }
#pragma unroll
    for (int t = 0; t < 8; t++) {
        int f = tid + t * 256;
        int k = f >> 5, c = (f & 31) << 2;
        cp16(wb0 + k * 132 + c, Wt + k * 128 + c);      // Wz half0
    }
    CP_COMMIT();                           // G0
    cp_half(wb1, Wt + 64 * 128);           // G1 = Wz1... wait: halves per weight
    // NOTE: half i of weight w lives at Wt + w*16384 + (i)*64*128. Here G1 must
    // be Wz half1:
    // (cp_half above loaded Wt + 8192 = Wz rows 64..127 — correct.)
    if (tid < 128) {
        sBz[tid] = Wz_b[tid] + Uz_b[tid];
        sBr[tid] = Wr_b[tid] + Ur_b[tid];
        sBh[tid] = Wh_b[tid] + Uh_b[tid];
    }

    ull arrA[8][4], arrB[8][4];
    float* zF = (float*)arrA;              // reg-array alias for parked floats

    // STEP(i): wait half i ready, compute into acc with operand A, prefetch i+2
#define STEPQ(i, Aptr, acc) do { \
        CP_WAIT(1); __syncthreads(); \
        mma_half<132>(Aptr, wb[(i) & 1], ((i) & 1) * 64, r0, c0, acc); \
        __syncthreads(); \
        if ((i) + 2 <= 13) cp_half(wb[(i) & 1], Wt + (((i) + 2) >> 1) * 16384 + (((i) + 2) & 1) * 8192); \
    } while (0)

    // ---- z = sigma(neigh@Wz + h@Uz + bz) ----
    zero_acc8(arrA);
    STEPQ(0, sN, arrA);                    // Wz half0
    STEPQ(1, sN, arrA);                    // Wz half1
    STEPQ(2, sH, arrA);                    // Uz half0
    STEPQ(3, sH, arrA);                    // Uz half1
#pragma unroll
    for (int i = 0; i < 8; i++) {          // z -> global scratch (own cells)
        float o[8]; row_to_f8(arrA[i], o);
        float z0[4], z1[4];
#pragma unroll
        for (int j = 0; j < 8; j++) {
            float zv = sigmoidf_(o[j] + sBz[colof(c0, j)]);
            if (j < 4) z0[j] = zv; else z1[j - 4] = zv;
        }
        float* zr = zbuf + (base + r0 + i) * ND;
        *(float4*)(zr + c0)      = make_float4(z0[0], z0[1], z0[2], z0[3]);
        *(float4*)(zr + c0 + 64) = make_float4(z1[0], z1[1], z1[2], z1[3]);
    }
    // ---- r = sigma(neigh@Wr + h@Ur + br) ----
    zero_acc8(arrA);
    STEPQ(4, sN, arrA);                    // Wr0
    STEPQ(5, sN, arrA);                    // Wr1
    STEPQ(6, sH, arrA);                    // Ur0
    STEPQ(7, sH, arrA);                    // Ur1
    // rh = r * h, parked in arrA as floats (own cells; h from sH)
#pragma unroll
    for (int i = 0; i < 8; i++) {
        float o[8]; row_to_f8(arrA[i], o);
#pragma unroll
        for (int j = 0; j < 8; j++) {
            int col = colof(c0, j);
            float rv = sigmoidf_(o[j] + sBr[col]);
            zF[i * 8 + j] = rv * sH[(r0 + i) * 132 + col];
        }
    }
    // ---- hhat partial: neigh@Wh (last neigh use) ----
    zero_acc8(arrB);
    STEPQ(8, sN, arrB);                    // Wh0
    STEPQ(9, sN, arrB);                    // Wh1
    // write rh into sN (own cells), then reload z into the freed arrA
#pragma unroll
    for (int i = 0; i < 8; i++) {
        sN[(r0 + i) * 132 + c0 + 0] = zF[i * 8 + 0];
        sN[(r0 + i) * 132 + c0 + 1] = zF[i * 8 + 1];
        sN[(r0 + i) * 132 + c0 + 2] = zF[i * 8 + 2];
        sN[(r0 + i) * 132 + c0 + 3] = zF[i * 8 + 3];
        sN[(r0 + i) * 132 + c0 + 64] = zF[i * 8 + 4];
        sN[(r0 + i) * 132 + c0 + 65] = zF[i * 8 + 5];
        sN[(r0 + i) * 132 + c0 + 66] = zF[i * 8 + 6];
        sN[(r0 + i) * 132 + c0 + 67] = zF[i * 8 + 7];
    }
#pragma unroll
    for (int i = 0; i < 8; i++) {          // z reload (L2-hot, own cells)
        const float* zr = zbuf + (base + r0 + i) * ND;
        float4 a = *(const float4*)(zr + c0);
        float4 b2 = *(const float4*)(zr + c0 + 64);
        zF[i * 8 + 0] = a.x; zF[i * 8 + 1] = a.y; zF[i * 8 + 2] = a.z; zF[i * 8 + 3] = a.w;
        zF[i * 8 + 4] = b2.x; zF[i * 8 + 5] = b2.y; zF[i * 8 + 6] = b2.z; zF[i * 8 + 7] = b2.w;
    }
    // ---- hhat += rh@Uh ----  (STEPQ entry sync makes rh visible)
    STEPQ(10, sN, arrB);                   // Uh0
    STEPQ(11, sN, arrB);                   // Uh1
    // ---- combine: h' = h + z*(hhat - h); write h_out, stage h' in sN ----
#pragma unroll
    for (int i = 0; i < 8; i++) {
        float o[8]; row_to_f8(arrB[i], o);
        float hn[8];
#pragma unroll
        for (int j = 0; j < 8; j++) {
            int col = colof(c0, j);
            float hh = tanhf(o[j] + sBh[col]);
            float h = sH[(r0 + i) * 132 + col];
            hn[j] = fmaf(zF[i * 8 + j], hh - h, h);
            sN[(r0 + i) * 132 + col] = hn[j];
        }
        float* orow = h_out + (base + r0 + i) * ND;
        *(float4*)(orow + c0)      = make_float4(hn[0], hn[1], hn[2], hn[3]);
        *(float4*)(orow + c0 + 64) = make_float4(hn[4], hn[5], hn[6], hn[7]);
    }
    if (do_hp) {
        // ---- hp = h' @ Wp^T ----
        zero_acc8(arrA);
        STEPQ(12, sN, arrA);               // Wp0
        CP_WAIT(0); __syncthreads();
        mma_half<132>(sN, wb[1], 64, r0, c0, arrA);     // Wp1 (no prefetch after)
#pragma unroll
        for (int i = 0; i < 8; i++) {
            float o[8]; row_to_f8(arrA[i], o);
            float* orow = hp_out + (base + r0 + i) * ND;
            *(float4*)(orow + c0)      = make_float4(o[0], o[1], o[2], o[3]);
            *(float4*)(orow + c0 + 64) = make_float4(o[4], o[5], o[6], o[7]);
        }
    } else {
        CP_WAIT(0);                        // drain ledger before exit
    }
#undef STEPQ
}

// ---------------------------------------------------------------------------
extern "C" void kernel_launch(void* const* d_in, const int* in_sizes, int n_in,
                              void* d_out, int out_size) {
    const float* init_node = (const float*)d_in[0];
    const float* mask      = (const float*)d_in[1];
    // d_in[2] = n_steps (fixed at 5 by the problem definition)
    const float* Wp_w = (const float*)d_in[3];
    const float* Wp_b = (const float*)d_in[4];
    const float* Wz_w = (const float*)d_in[5];
    const float* Wz_b = (const float*)d_in[6];
    const float* Uz_w = (const float*)d_in[7];
    const float* Uz_b = (const float*)d_in[8];
    const float* Wr_w = (const float*)d_in[9];
    const float* Wr_b = (const float*)d_in[10];
    const float* Ur_w = (const float*)d_in[11];
    const float* Ur_b = (const float*)d_in[12];
    const float* Wh_w = (const float*)d_in[13];
    const float* Wh_b = (const float*)d_in[14];
    const float* Uh_w = (const float*)d_in[15];
    const float* Uh_b = (const float*)d_in[16];
    float* hout = (float*)d_out;

    float *g_hp_p, *g_neigh_p, *g_Wt_p, *g_z_p;
    cudaGetSymbolAddress((void**)&g_hp_p, g_hp);
    cudaGetSymbolAddress((void**)&g_neigh_p, g_neigh);
    cudaGetSymbolAddress((void**)&g_Wt_p, g_Wt);
    cudaGetSymbolAddress((void**)&g_z_p, g_z);

    cudaFuncSetAttribute(gru_kernel,      cudaFuncAttributeMaxDynamicSharedMemorySize, GRU_SMEM);
    cudaFuncSetAttribute(xw_kernel,       cudaFuncAttributeMaxDynamicSharedMemorySize, XW_SMEM);
    cudaFuncSetAttribute(maskgemm_kernel, cudaFuncAttributeMaxDynamicSharedMemorySize, MG_SMEM);

    transpose_weights_kernel<<<7, 256>>>(Wz_w, Uz_w, Wr_w, Ur_w, Wh_w, Uh_w, Wp_w);
    xw_kernel<<<NROWS / 128, 256, XW_SMEM>>>(init_node, g_Wt_p + 6 * ND * ND, g_hp_p);

    for (int s = 0; s < NSTEPS; s++) {
        maskgemm_kernel<<<dim3(NN / 128, NB), 256, MG_SMEM>>>(mask, g_hp_p, Wp_b, g_neigh_p);
        gru_kernel<<<NROWS / 128, 256, GRU_SMEM>>>(
            g_neigh_p, (s == 0) ? init_node : hout, hout, g_hp_p, g_z_p,
            g_Wt_p, Wz_b, Uz_b, Wr_b, Ur_b, Wh_b, Uh_b, (s < NSTEPS - 1) ? 1 : 0);
    }
}